// round 14
// baseline (speedup 1.0000x reference)
#include <cuda_runtime.h>
#include <cuda_fp16.h>
#include <cstdint>

// Problem constants
#define NP    8100      // patches per image (90*90)
#define NPD   8104      // padded D row stride (halves), multiple of 8 for uint4
#define HP    90        // patch grid side
#define PB    7         // patch size
#define DFEAT 147       // 3*7*7
#define KP    168       // padded K (halves); 336B rows -> conflict-free ldmatrix
#define KV4   21        // uint4 per padded row (168*2/16)

// ---------------- device scratch (static; no allocations allowed) ----------
__device__ __half   g_Xp[2][NP][KP];
__device__ __half   g_Yp[2][NP][KP];
__device__ float    g_Sx[2][NP];
__device__ float    g_Sy[2][NP];
__device__ unsigned g_rowMin[2][NP];
__device__ unsigned g_colMin[2][NP];
__device__ __half   g_D[(size_t)2 * NP * NPD];   // ~262.6 MB fp16 dist (pre-normalization)

// monotone float<->uint mapping so atomicMin(unsigned) == float min
__device__ __forceinline__ unsigned fkey(float f) {
    unsigned u = __float_as_uint(f);
    return (u & 0x80000000u) ? ~u : (u | 0x80000000u);
}
__device__ __forceinline__ float funkey(unsigned k) {
    unsigned u = (k & 0x80000000u) ? (k & 0x7FFFFFFFu) : ~k;
    return __uint_as_float(u);
}

__device__ __forceinline__ void ldsm4(unsigned& r0, unsigned& r1, unsigned& r2, unsigned& r3,
                                      uint32_t addr) {
    asm volatile("ldmatrix.sync.aligned.m8n8.x4.shared.b16 {%0,%1,%2,%3}, [%4];\n"
                 : "=r"(r0), "=r"(r1), "=r"(r2), "=r"(r3) : "r"(addr));
}
__device__ __forceinline__ void mma16816(float* d, const unsigned* a, const unsigned* b) {
    asm volatile("mma.sync.aligned.m16n8k16.row.col.f32.f16.f16.f32 "
                 "{%0,%1,%2,%3},{%4,%5,%6,%7},{%8,%9},{%0,%1,%2,%3};\n"
                 : "+f"(d[0]), "+f"(d[1]), "+f"(d[2]), "+f"(d[3])
                 : "r"(a[0]), "r"(a[1]), "r"(a[2]), "r"(a[3]), "r"(b[0]), "r"(b[1]));
}
__device__ __forceinline__ void cp16(uint32_t smem, const void* gmem) {
    asm volatile("cp.async.cg.shared.global [%0], [%1], 16;\n"
                 :: "r"(smem), "l"(gmem));
}
// write-through store: D lines never sit dirty in L2
__device__ __forceinline__ void stwt32(void* p, unsigned v) {
    asm volatile("st.global.wt.b32 [%0], %1;\n" :: "l"(p), "r"(v) : "memory");
}

// ---------------- kernel 1: patch extraction (fp16 rounding) + min init ----
__global__ void k_extract(const float* __restrict__ x, const float* __restrict__ y) {
    int idx = blockIdx.x * blockDim.x + threadIdx.x;
    if (idx < 2 * NP) {
        (&g_rowMin[0][0])[idx] = 0xFFFFFFFFu;
        (&g_colMin[0][0])[idx] = 0xFFFFFFFFu;
    }
    const int total = 2 * NP * KP;
    if (idx >= total) return;
    int b   = idx / (NP * KP);
    int rem = idx % (NP * KP);
    int n   = rem / KP;
    int k   = rem % KP;
    __half hx = __float2half(0.0f), hy = hx;
    if (k < DFEAT) {
        int c  = k / 49;
        int kk = k % 49;
        int dy = kk / PB, dx = kk % PB;
        int py = n / HP,  px = n % HP;
        int off = ((b * 3 + c) * 96 + (py + dy)) * 96 + (px + dx);
        hx = __float2half(x[off]);
        hy = __float2half(y[off]);
    }
    (&g_Xp[0][0][0])[idx] = hx;
    (&g_Yp[0][0][0])[idx] = hy;
}

// ---------------- kernel 2: per-row squared norms (fp32 acc over fp16 data) -
__global__ void k_sums() {
    int gw   = blockIdx.x * (blockDim.x >> 5) + (threadIdx.x >> 5);
    int lane = threadIdx.x & 31;
    const int totalRows = 2 * 2 * NP;   // (X,Y) x batch x NP
    if (gw >= totalRows) return;
    int tsel = gw / (2 * NP);
    int rem  = gw % (2 * NP);
    int b    = rem / NP;
    int n    = rem % NP;
    const __half* row = tsel ? &g_Yp[b][n][0] : &g_Xp[b][n][0];
    float s = 0.f;
    for (int k = lane; k < DFEAT; k += 32) {
        float v = __half2float(row[k]);
        s += v * v;
    }
    #pragma unroll
    for (int o = 16; o; o >>= 1) s += __shfl_xor_sync(0xFFFFFFFFu, s, o);
    if (lane == 0) {
        if (tsel) g_Sy[b][n] = s; else g_Sx[b][n] = s;
    }
}

// ---------------- kernel 3: dist GEMM via HMMA (fused store + rowmin) ------
// round-5 proven shape: 128x128 block, 256 threads = 8 warps (4m x 2n),
// warp tile m32 x n64, f32 accumulators; D stores via st.wt.
__global__ void k_dist() {
    extern __shared__ __half smemBuf[];
    __half* Ys = smemBuf;                      // 128 x KP
    __half* Xs = smemBuf + 128 * KP;           // 128 x KP
    float* sSy = (float*)(smemBuf + 2 * 128 * KP);
    float* sSx = sSy + 128;

    const int tid  = threadIdx.x;
    const int lane = tid & 31;
    const int wid  = tid >> 5;
    const int b    = blockIdx.z;
    const int rowBase = blockIdx.y * 128;   // targets (Y)
    const int colBase = blockIdx.x * 128;   // inputs  (X)

    // cooperative load via cp.async: 128 rows x 21 uint4 per operand
    const uint4* ybase = (const uint4*)&g_Yp[b][0][0];
    const uint4* xbase = (const uint4*)&g_Xp[b][0][0];
    uint32_t ysAddr = (uint32_t)__cvta_generic_to_shared(Ys);
    uint32_t xsAddr = (uint32_t)__cvta_generic_to_shared(Xs);
    #pragma unroll 3
    for (int idx = tid; idx < 128 * KV4; idx += 256) {
        int r = idx / KV4, c = idx % KV4;
        int gy = min(rowBase + r, NP - 1);
        int gx = min(colBase + r, NP - 1);
        cp16(ysAddr + idx * 16u, &ybase[(size_t)gy * KV4 + c]);
        cp16(xsAddr + idx * 16u, &xbase[(size_t)gx * KV4 + c]);
    }
    asm volatile("cp.async.commit_group;\n" ::: "memory");
    if (tid < 128) sSy[tid] = g_Sy[b][min(rowBase + tid, NP - 1)];
    else           sSx[tid - 128] = g_Sx[b][min(colBase + tid - 128, NP - 1)];
    asm volatile("cp.async.wait_group 0;\n" ::: "memory");
    __syncthreads();

    const int warpM = (wid >> 1) * 32;
    const int warpN = (wid & 1) * 64;

    // ldmatrix per-lane addresses
    int aRow = warpM + (lane & 15);
    uint32_t aAddr0 = ysAddr + (uint32_t)(aRow * KP + (lane >> 4) * 8) * 2u;
    uint32_t aAddr1 = aAddr0 + 16u * KP * 2u;
    int bRow = warpN + (lane & 7) + ((lane >> 4) & 1) * 8;
    int bKc  = (lane >> 3) & 1;
    uint32_t bAddr[4];
    #pragma unroll
    for (int p = 0; p < 4; p++)
        bAddr[p] = xsAddr + (uint32_t)((bRow + p * 16) * KP + bKc * 8) * 2u;

    float acc[2][8][4];
    #pragma unroll
    for (int mi = 0; mi < 2; mi++)
        #pragma unroll
        for (int ni = 0; ni < 8; ni++)
            #pragma unroll
            for (int q = 0; q < 4; q++) acc[mi][ni][q] = 0.f;

    #pragma unroll
    for (int ks = 0; ks < 10; ks++) {
        uint32_t koff = (uint32_t)ks * 32u;   // 16 halves
        unsigned af[2][4];
        ldsm4(af[0][0], af[0][1], af[0][2], af[0][3], aAddr0 + koff);
        ldsm4(af[1][0], af[1][1], af[1][2], af[1][3], aAddr1 + koff);
        unsigned bf[4][4];  // bf[p][0..1] -> ni=2p, bf[p][2..3] -> ni=2p+1
        #pragma unroll
        for (int p = 0; p < 4; p++)
            ldsm4(bf[p][0], bf[p][1], bf[p][2], bf[p][3], bAddr[p] + koff);
        #pragma unroll
        for (int mi = 0; mi < 2; mi++)
            #pragma unroll
            for (int ni = 0; ni < 8; ni++)
                mma16816(acc[mi][ni], af[mi], &bf[ni >> 1][(ni & 1) * 2]);
    }

    // epilogue: dist, fp16 round, write-through store D, rowmin
    const float invd = 1.0f / 147.0f;
    const int qr = lane >> 2, qc = lane & 3;
    __half* Db = &g_D[(size_t)b * NP * NPD];
    #pragma unroll
    for (int mi = 0; mi < 2; mi++) {
        int lr0 = warpM + mi * 16 + qr;
        int lr1 = lr0 + 8;
        int gt0 = rowBase + lr0, gt1 = rowBase + lr1;
        float sy0 = sSy[lr0], sy1 = sSy[lr1];
        float lm0 = __int_as_float(0x7F800000), lm1 = lm0;
        #pragma unroll
        for (int ni = 0; ni < 8; ni++) {
            int lc = warpN + ni * 8 + qc * 2;
            int gi = colBase + lc;
            if (gi < NP) {                       // NP even, pair stays in-range together
                float sx0 = sSx[lc], sx1 = sSx[lc + 1];
                if (gt0 < NP) {
                    __half h0 = __float2half((sy0 + sx0 - 2.0f * acc[mi][ni][0]) * invd);
                    __half h1 = __float2half((sy0 + sx1 - 2.0f * acc[mi][ni][1]) * invd);
                    __half2 hh = __halves2half2(h0, h1);
                    stwt32(&Db[(size_t)gt0 * NPD + gi], *(unsigned*)&hh);
                    lm0 = fminf(lm0, fminf(__half2float(h0), __half2float(h1)));
                }
                if (gt1 < NP) {
                    __half h2 = __float2half((sy1 + sx0 - 2.0f * acc[mi][ni][2]) * invd);
                    __half h3 = __float2half((sy1 + sx1 - 2.0f * acc[mi][ni][3]) * invd);
                    __half2 hh = __halves2half2(h2, h3);
                    stwt32(&Db[(size_t)gt1 * NPD + gi], *(unsigned*)&hh);
                    lm1 = fminf(lm1, fminf(__half2float(h2), __half2float(h3)));
                }
            }
        }
        #pragma unroll
        for (int o = 2; o; o >>= 1) {
            lm0 = fminf(lm0, __shfl_xor_sync(0xFFFFFFFFu, lm0, o));
            lm1 = fminf(lm1, __shfl_xor_sync(0xFFFFFFFFu, lm1, o));
        }
        if (qc == 0) {
            if (gt0 < NP) atomicMin(&g_rowMin[b][gt0], fkey(lm0));
            if (gt1 < NP) atomicMin(&g_rowMin[b][gt1], fkey(lm1));
        }
    }
}

// ---------------- kernel 4: column-min of dist/(rowmin+alpha) --------------
// 8 cols/thread (one uint4 per row), rows unrolled x8 -> 8 independent
// LDG.128 in flight per thread at ~4 CTAs/SM residency.
#define CM_CHUNK 64
__device__ __forceinline__ void cm_acc4(float* m, const uint4& v, float inv) {
    float2 f0 = __half22float2(*(const __half2*)&v.x);
    float2 f1 = __half22float2(*(const __half2*)&v.y);
    float2 f2 = __half22float2(*(const __half2*)&v.z);
    float2 f3 = __half22float2(*(const __half2*)&v.w);
    m[0] = fminf(m[0], f0.x * inv); m[1] = fminf(m[1], f0.y * inv);
    m[2] = fminf(m[2], f1.x * inv); m[3] = fminf(m[3], f1.y * inv);
    m[4] = fminf(m[4], f2.x * inv); m[5] = fminf(m[5], f2.y * inv);
    m[6] = fminf(m[6], f3.x * inv); m[7] = fminf(m[7], f3.y * inv);
}
__global__ void k_colmin() {
    __shared__ float sInv[CM_CHUNK];
    const int tid = threadIdx.x;
    const int b   = blockIdx.z;
    const int t0  = blockIdx.y * CM_CHUNK;
    const int nrows = min(CM_CHUNK, NP - t0);
    const float alpha = __half2float(__float2half(0.05f));  // f16-rounded ALPHA

    if (tid < nrows)
        sInv[tid] = 1.0f / (funkey(g_rowMin[b][t0 + tid]) + alpha);
    __syncthreads();

    const int col0 = (blockIdx.x * 256 + tid) * 8;
    if (col0 >= NP) return;
    const bool full = (col0 + 8 <= NPD);   // always true for col0 <= 8096

    float m[8];
    #pragma unroll
    for (int j = 0; j < 8; j++) m[j] = __int_as_float(0x7F800000);

    const __half* Db = &g_D[(size_t)b * NP * NPD];
    if (full) {
        const char* base = (const char*)(Db + (size_t)t0 * NPD + col0);
        const size_t stride = (size_t)NPD * sizeof(__half);
        int r = 0;
        for (; r + 8 <= nrows; r += 8) {
            uint4 v[8];
            #pragma unroll
            for (int u = 0; u < 8; u++)
                v[u] = __ldcs((const uint4*)(base + (size_t)(r + u) * stride));
            #pragma unroll
            for (int u = 0; u < 8; u++)
                cm_acc4(m, v[u], sInv[r + u]);
        }
        for (; r < nrows; r++) {
            uint4 v = __ldcs((const uint4*)(base + (size_t)r * stride));
            cm_acc4(m, v, sInv[r]);
        }
    }
    #pragma unroll
    for (int j = 0; j < 8; j++)
        if (col0 + j < NP) atomicMin(&g_colMin[b][col0 + j], fkey(m[j]));
}

// ---------------- kernel 5: final mean, write scalar (fp32 output) ---------
__global__ void k_final(float* __restrict__ out) {
    __shared__ float r0[512], r1[512];
    int tid = threadIdx.x;
    float s0 = 0.f, s1 = 0.f;
    for (int i = tid; i < NP; i += 512) {
        s0 += funkey(g_colMin[0][i]);
        s1 += funkey(g_colMin[1][i]);
    }
    r0[tid] = s0; r1[tid] = s1;
    __syncthreads();
    for (int o = 256; o; o >>= 1) {
        if (tid < o) { r0[tid] += r0[tid + o]; r1[tid] += r1[tid + o]; }
        __syncthreads();
    }
    if (tid == 0) {
        float loss = (r0[0] + r1[0]) / (2.0f * NP);
        out[0] = loss;
    }
}

// ---------------- launch ---------------------------------------------------
extern "C" void kernel_launch(void* const* d_in, const int* in_sizes, int n_in,
                              void* d_out, int out_size) {
    const float* x = (const float*)d_in[0];
    const float* y = (const float*)d_in[1];
    float* out = (float*)d_out;

    const int distSmem = 2 * 128 * KP * 2 + 2 * 128 * 4;   // 87040 B
    cudaFuncSetAttribute(k_dist, cudaFuncAttributeMaxDynamicSharedMemorySize, distSmem);

    {
        int total = 2 * NP * KP;
        k_extract<<<(total + 255) / 256, 256>>>(x, y);
    }
    {
        int rows = 2 * 2 * NP;                 // 32400 rows, 8 warps/block
        k_sums<<<(rows + 7) / 8, 256>>>();
    }
    {
        dim3 grid((NP + 127) / 128, (NP + 127) / 128, 2);   // 64 x 64 x 2
        k_dist<<<grid, 256, distSmem>>>();
    }
    {
        dim3 grid((NP + 2047) / 2048, (NP + CM_CHUNK - 1) / CM_CHUNK, 2);   // 4 x 127 x 2
        k_colmin<<<grid, 256>>>();
    }
    k_final<<<1, 512>>>(out);
}

// round 15
// speedup vs baseline: 1.0286x; 1.0286x over previous
#include <cuda_runtime.h>
#include <cuda_fp16.h>
#include <cstdint>

// Problem constants
#define NP    8100      // patches per image (90*90)
#define NPD   8104      // padded D row stride (halves), multiple of 8 for uint4
#define HP    90        // patch grid side
#define PB    7         // patch size
#define DFEAT 147       // 3*7*7
#define KP    168       // padded K (halves); 336B rows -> conflict-free ldmatrix
#define KV4   21        // uint4 per padded row (168*2/16)

// ---------------- device scratch (static; no allocations allowed) ----------
__device__ __half   g_Xp[2][NP][KP];
__device__ __half   g_Yp[2][NP][KP];
__device__ float    g_Sx[2][NP];
__device__ float    g_Sy[2][NP];
__device__ unsigned g_rowMin[2][NP];
__device__ unsigned g_colMin[2][NP];
__device__ __half   g_D[(size_t)2 * NP * NPD];   // ~262.6 MB fp16 dist (pre-normalization)

// monotone float<->uint mapping so atomicMin(unsigned) == float min
__device__ __forceinline__ unsigned fkey(float f) {
    unsigned u = __float_as_uint(f);
    return (u & 0x80000000u) ? ~u : (u | 0x80000000u);
}
__device__ __forceinline__ float funkey(unsigned k) {
    unsigned u = (k & 0x80000000u) ? (k & 0x7FFFFFFFu) : ~k;
    return __uint_as_float(u);
}

__device__ __forceinline__ void ldsm4(unsigned& r0, unsigned& r1, unsigned& r2, unsigned& r3,
                                      uint32_t addr) {
    asm volatile("ldmatrix.sync.aligned.m8n8.x4.shared.b16 {%0,%1,%2,%3}, [%4];\n"
                 : "=r"(r0), "=r"(r1), "=r"(r2), "=r"(r3) : "r"(addr));
}
__device__ __forceinline__ void mma16816(float* d, const unsigned* a, const unsigned* b) {
    asm volatile("mma.sync.aligned.m16n8k16.row.col.f32.f16.f16.f32 "
                 "{%0,%1,%2,%3},{%4,%5,%6,%7},{%8,%9},{%0,%1,%2,%3};\n"
                 : "+f"(d[0]), "+f"(d[1]), "+f"(d[2]), "+f"(d[3])
                 : "r"(a[0]), "r"(a[1]), "r"(a[2]), "r"(a[3]), "r"(b[0]), "r"(b[1]));
}
__device__ __forceinline__ void cp16(uint32_t smem, const void* gmem) {
    asm volatile("cp.async.cg.shared.global [%0], [%1], 16;\n"
                 :: "r"(smem), "l"(gmem));
}
// coalesced write-through 128-bit store
__device__ __forceinline__ void stwt128(void* p, uint4 v) {
    asm volatile("st.global.wt.v4.b32 [%0], {%1,%2,%3,%4};\n"
                 :: "l"(p), "r"(v.x), "r"(v.y), "r"(v.z), "r"(v.w) : "memory");
}

// ---------------- kernel 1: patch extraction (fp16 rounding) + min init ----
__global__ void k_extract(const float* __restrict__ x, const float* __restrict__ y) {
    int idx = blockIdx.x * blockDim.x + threadIdx.x;
    if (idx < 2 * NP) {
        (&g_rowMin[0][0])[idx] = 0xFFFFFFFFu;
        (&g_colMin[0][0])[idx] = 0xFFFFFFFFu;
    }
    const int total = 2 * NP * KP;
    if (idx >= total) return;
    int b   = idx / (NP * KP);
    int rem = idx % (NP * KP);
    int n   = rem / KP;
    int k   = rem % KP;
    __half hx = __float2half(0.0f), hy = hx;
    if (k < DFEAT) {
        int c  = k / 49;
        int kk = k % 49;
        int dy = kk / PB, dx = kk % PB;
        int py = n / HP,  px = n % HP;
        int off = ((b * 3 + c) * 96 + (py + dy)) * 96 + (px + dx);
        hx = __float2half(x[off]);
        hy = __float2half(y[off]);
    }
    (&g_Xp[0][0][0])[idx] = hx;
    (&g_Yp[0][0][0])[idx] = hy;
}

// ---------------- kernel 2: per-row squared norms (fp32 acc over fp16 data) -
__global__ void k_sums() {
    int gw   = blockIdx.x * (blockDim.x >> 5) + (threadIdx.x >> 5);
    int lane = threadIdx.x & 31;
    const int totalRows = 2 * 2 * NP;   // (X,Y) x batch x NP
    if (gw >= totalRows) return;
    int tsel = gw / (2 * NP);
    int rem  = gw % (2 * NP);
    int b    = rem / NP;
    int n    = rem % NP;
    const __half* row = tsel ? &g_Yp[b][n][0] : &g_Xp[b][n][0];
    float s = 0.f;
    for (int k = lane; k < DFEAT; k += 32) {
        float v = __half2float(row[k]);
        s += v * v;
    }
    #pragma unroll
    for (int o = 16; o; o >>= 1) s += __shfl_xor_sync(0xFFFFFFFFu, s, o);
    if (lane == 0) {
        if (tsel) g_Sy[b][n] = s; else g_Sx[b][n] = s;
    }
}

// ---------------- kernel 3: dist GEMM via HMMA (fused store + rowmin) ------
// round-5 proven shape: 128x128 block, 256 threads = 8 warps (4m x 2n),
// warp tile m32 x n64, f32 accumulators. Epilogue stages the f16 tile in
// smem (272B row stride, conflict-free) then stores D with coalesced
// st.global.wt.v4 (8 per thread).
#define TS 136   // staged tile row stride in halves (272 B)
__global__ void k_dist() {
    extern __shared__ __half smemBuf[];
    __half* Ys = smemBuf;                      // 128 x KP (reused as staging tile)
    __half* Xs = smemBuf + 128 * KP;           // 128 x KP
    float* sSy = (float*)(smemBuf + 2 * 128 * KP);
    float* sSx = sSy + 128;

    const int tid  = threadIdx.x;
    const int lane = tid & 31;
    const int wid  = tid >> 5;
    const int b    = blockIdx.z;
    const int rowBase = blockIdx.y * 128;   // targets (Y)
    const int colBase = blockIdx.x * 128;   // inputs  (X)

    // cooperative load via cp.async: 128 rows x 21 uint4 per operand
    const uint4* ybase = (const uint4*)&g_Yp[b][0][0];
    const uint4* xbase = (const uint4*)&g_Xp[b][0][0];
    uint32_t ysAddr = (uint32_t)__cvta_generic_to_shared(Ys);
    uint32_t xsAddr = (uint32_t)__cvta_generic_to_shared(Xs);
    #pragma unroll 3
    for (int idx = tid; idx < 128 * KV4; idx += 256) {
        int r = idx / KV4, c = idx % KV4;
        int gy = min(rowBase + r, NP - 1);
        int gx = min(colBase + r, NP - 1);
        cp16(ysAddr + idx * 16u, &ybase[(size_t)gy * KV4 + c]);
        cp16(xsAddr + idx * 16u, &xbase[(size_t)gx * KV4 + c]);
    }
    asm volatile("cp.async.commit_group;\n" ::: "memory");
    if (tid < 128) sSy[tid] = g_Sy[b][min(rowBase + tid, NP - 1)];
    else           sSx[tid - 128] = g_Sx[b][min(colBase + tid - 128, NP - 1)];
    asm volatile("cp.async.wait_group 0;\n" ::: "memory");
    __syncthreads();

    const int warpM = (wid >> 1) * 32;
    const int warpN = (wid & 1) * 64;

    // ldmatrix per-lane addresses
    int aRow = warpM + (lane & 15);
    uint32_t aAddr0 = ysAddr + (uint32_t)(aRow * KP + (lane >> 4) * 8) * 2u;
    uint32_t aAddr1 = aAddr0 + 16u * KP * 2u;
    int bRow = warpN + (lane & 7) + ((lane >> 4) & 1) * 8;
    int bKc  = (lane >> 3) & 1;
    uint32_t bAddr[4];
    #pragma unroll
    for (int p = 0; p < 4; p++)
        bAddr[p] = xsAddr + (uint32_t)((bRow + p * 16) * KP + bKc * 8) * 2u;

    float acc[2][8][4];
    #pragma unroll
    for (int mi = 0; mi < 2; mi++)
        #pragma unroll
        for (int ni = 0; ni < 8; ni++)
            #pragma unroll
            for (int q = 0; q < 4; q++) acc[mi][ni][q] = 0.f;

    #pragma unroll
    for (int ks = 0; ks < 10; ks++) {
        uint32_t koff = (uint32_t)ks * 32u;   // 16 halves
        unsigned af[2][4];
        ldsm4(af[0][0], af[0][1], af[0][2], af[0][3], aAddr0 + koff);
        ldsm4(af[1][0], af[1][1], af[1][2], af[1][3], aAddr1 + koff);
        unsigned bf[4][4];  // bf[p][0..1] -> ni=2p, bf[p][2..3] -> ni=2p+1
        #pragma unroll
        for (int p = 0; p < 4; p++)
            ldsm4(bf[p][0], bf[p][1], bf[p][2], bf[p][3], bAddr[p] + koff);
        #pragma unroll
        for (int mi = 0; mi < 2; mi++)
            #pragma unroll
            for (int ni = 0; ni < 8; ni++)
                mma16816(acc[mi][ni], af[mi], &bf[ni >> 1][(ni & 1) * 2]);
    }

    // ---- epilogue phase 1: compute dist, stage f16 tile in smem, rowmin ----
    __syncthreads();                 // operand smem now dead; reuse Ys
    __half* tile = Ys;
    const float invd = 1.0f / 147.0f;
    const int qr = lane >> 2, qc = lane & 3;
    __half* Db = &g_D[(size_t)b * NP * NPD];
    // NOTE: out-of-range rows/cols hold clamped duplicates of row/col NP-1,
    // so including them in mins is a no-op; no per-element guards needed.
    #pragma unroll
    for (int mi = 0; mi < 2; mi++) {
        int lr0 = warpM + mi * 16 + qr;
        int lr1 = lr0 + 8;
        float sy0 = sSy[lr0], sy1 = sSy[lr1];
        float lm0 = __int_as_float(0x7F800000), lm1 = lm0;
        #pragma unroll
        for (int ni = 0; ni < 8; ni++) {
            int lc = warpN + ni * 8 + qc * 2;
            float sx0 = sSx[lc], sx1 = sSx[lc + 1];
            __half h0 = __float2half((sy0 + sx0 - 2.0f * acc[mi][ni][0]) * invd);
            __half h1 = __float2half((sy0 + sx1 - 2.0f * acc[mi][ni][1]) * invd);
            *(__half2*)&tile[lr0 * TS + lc] = __halves2half2(h0, h1);
            lm0 = fminf(lm0, fminf(__half2float(h0), __half2float(h1)));
            __half h2 = __float2half((sy1 + sx0 - 2.0f * acc[mi][ni][2]) * invd);
            __half h3 = __float2half((sy1 + sx1 - 2.0f * acc[mi][ni][3]) * invd);
            *(__half2*)&tile[lr1 * TS + lc] = __halves2half2(h2, h3);
            lm1 = fminf(lm1, fminf(__half2float(h2), __half2float(h3)));
        }
        #pragma unroll
        for (int o = 2; o; o >>= 1) {
            lm0 = fminf(lm0, __shfl_xor_sync(0xFFFFFFFFu, lm0, o));
            lm1 = fminf(lm1, __shfl_xor_sync(0xFFFFFFFFu, lm1, o));
        }
        if (qc == 0) {
            int gt0 = rowBase + lr0, gt1 = rowBase + lr1;
            if (gt0 < NP) atomicMin(&g_rowMin[b][gt0], fkey(lm0));
            if (gt1 < NP) atomicMin(&g_rowMin[b][gt1], fkey(lm1));
        }
    }

    // ---- epilogue phase 2: coalesced uint4 stores of the staged tile ----
    __syncthreads();
    #pragma unroll
    for (int i = 0; i < 8; i++) {
        int idx = tid + 256 * i;         // 0..2047
        int row = idx >> 4;              // 0..127
        int c4  = idx & 15;              // uint4 index within row
        int gt   = rowBase + row;
        int gcol = colBase + c4 * 8;
        if (gt < NP && gcol + 8 <= NPD) {
            uint4 v = *(const uint4*)&tile[row * TS + c4 * 8];
            stwt128(&Db[(size_t)gt * NPD + gcol], v);
        }
    }
}

// ---------------- kernel 4: column-min of dist/(rowmin+alpha) --------------
// round-13 proven version: 8 cols/thread (one uint4/row), rows x4, 1016 CTAs
#define CM_CHUNK 64
__device__ __forceinline__ void cm_acc4(float* m, const uint4& v, float inv) {
    float2 f0 = __half22float2(*(const __half2*)&v.x);
    float2 f1 = __half22float2(*(const __half2*)&v.y);
    float2 f2 = __half22float2(*(const __half2*)&v.z);
    float2 f3 = __half22float2(*(const __half2*)&v.w);
    m[0] = fminf(m[0], f0.x * inv); m[1] = fminf(m[1], f0.y * inv);
    m[2] = fminf(m[2], f1.x * inv); m[3] = fminf(m[3], f1.y * inv);
    m[4] = fminf(m[4], f2.x * inv); m[5] = fminf(m[5], f2.y * inv);
    m[6] = fminf(m[6], f3.x * inv); m[7] = fminf(m[7], f3.y * inv);
}
__global__ void k_colmin() {
    __shared__ float sInv[CM_CHUNK];
    const int tid = threadIdx.x;
    const int b   = blockIdx.z;
    const int t0  = blockIdx.y * CM_CHUNK;
    const int nrows = min(CM_CHUNK, NP - t0);
    const float alpha = __half2float(__float2half(0.05f));  // f16-rounded ALPHA

    if (tid < nrows)
        sInv[tid] = 1.0f / (funkey(g_rowMin[b][t0 + tid]) + alpha);
    __syncthreads();

    const int col0 = (blockIdx.x * 256 + tid) * 8;
    if (col0 >= NP) return;
    const bool full = (col0 + 8 <= NPD);   // always true for col0 <= 8096

    float m[8];
    #pragma unroll
    for (int j = 0; j < 8; j++) m[j] = __int_as_float(0x7F800000);

    const __half* Db = &g_D[(size_t)b * NP * NPD];
    if (full) {
        const char* base = (const char*)(Db + (size_t)t0 * NPD + col0);
        const size_t stride = (size_t)NPD * sizeof(__half);
        int r = 0;
        for (; r + 4 <= nrows; r += 4) {
            uint4 v[4];
            #pragma unroll
            for (int u = 0; u < 4; u++)
                v[u] = __ldcs((const uint4*)(base + (size_t)(r + u) * stride));
            #pragma unroll
            for (int u = 0; u < 4; u++)
                cm_acc4(m, v[u], sInv[r + u]);
        }
        for (; r < nrows; r++) {
            uint4 v = __ldcs((const uint4*)(base + (size_t)r * stride));
            cm_acc4(m, v, sInv[r]);
        }
    }
    #pragma unroll
    for (int j = 0; j < 8; j++)
        if (col0 + j < NP) atomicMin(&g_colMin[b][col0 + j], fkey(m[j]));
}

// ---------------- kernel 5: final mean, write scalar (fp32 output) ---------
__global__ void k_final(float* __restrict__ out) {
    __shared__ float r0[512], r1[512];
    int tid = threadIdx.x;
    float s0 = 0.f, s1 = 0.f;
    for (int i = tid; i < NP; i += 512) {
        s0 += funkey(g_colMin[0][i]);
        s1 += funkey(g_colMin[1][i]);
    }
    r0[tid] = s0; r1[tid] = s1;
    __syncthreads();
    for (int o = 256; o; o >>= 1) {
        if (tid < o) { r0[tid] += r0[tid + o]; r1[tid] += r1[tid + o]; }
        __syncthreads();
    }
    if (tid == 0) {
        float loss = (r0[0] + r1[0]) / (2.0f * NP);
        out[0] = loss;
    }
}

// ---------------- launch ---------------------------------------------------
extern "C" void kernel_launch(void* const* d_in, const int* in_sizes, int n_in,
                              void* d_out, int out_size) {
    const float* x = (const float*)d_in[0];
    const float* y = (const float*)d_in[1];
    float* out = (float*)d_out;

    const int distSmem = 2 * 128 * KP * 2 + 2 * 128 * 4;   // 87040 B
    cudaFuncSetAttribute(k_dist, cudaFuncAttributeMaxDynamicSharedMemorySize, distSmem);

    {
        int total = 2 * NP * KP;
        k_extract<<<(total + 255) / 256, 256>>>(x, y);
    }
    {
        int rows = 2 * 2 * NP;                 // 32400 rows, 8 warps/block
        k_sums<<<(rows + 7) / 8, 256>>>();
    }
    {
        dim3 grid((NP + 127) / 128, (NP + 127) / 128, 2);   // 64 x 64 x 2
        k_dist<<<grid, 256, distSmem>>>();
    }
    {
        dim3 grid((NP + 2047) / 2048, (NP + CM_CHUNK - 1) / CM_CHUNK, 2);   // 4 x 127 x 2
        k_colmin<<<grid, 256>>>();
    }
    k_final<<<1, 512>>>(out);
}

// round 16
// speedup vs baseline: 1.0835x; 1.0533x over previous
#include <cuda_runtime.h>
#include <cuda_fp16.h>
#include <cstdint>

// Problem constants
#define NP    8100      // patches per image (90*90)
#define NPD   8104      // padded D row stride (halves), multiple of 8 for uint4
#define HP    90        // patch grid side
#define PB    7         // patch size
#define DFEAT 147       // 3*7*7
#define KP    168       // padded K (halves); 336B rows -> conflict-free ldmatrix
#define KV4   21        // uint4 per padded row (168*2/16)

// ---------------- device scratch (static; no allocations allowed) ----------
__device__ __half   g_Xp[2][NP][KP];
__device__ __half   g_Yp[2][NP][KP];
__device__ float    g_Sx[2][NP];
__device__ float    g_Sy[2][NP];
__device__ unsigned g_rowMin[2][NP];
__device__ unsigned g_colMin[2][NP];
__device__ __half   g_D[(size_t)2 * NP * NPD];   // ~262.6 MB fp16 dist (pre-normalization)

// monotone float<->uint mapping so atomicMin(unsigned) == float min
__device__ __forceinline__ unsigned fkey(float f) {
    unsigned u = __float_as_uint(f);
    return (u & 0x80000000u) ? ~u : (u | 0x80000000u);
}
__device__ __forceinline__ float funkey(unsigned k) {
    unsigned u = (k & 0x80000000u) ? (k & 0x7FFFFFFFu) : ~k;
    return __uint_as_float(u);
}

__device__ __forceinline__ void ldsm4(unsigned& r0, unsigned& r1, unsigned& r2, unsigned& r3,
                                      uint32_t addr) {
    asm volatile("ldmatrix.sync.aligned.m8n8.x4.shared.b16 {%0,%1,%2,%3}, [%4];\n"
                 : "=r"(r0), "=r"(r1), "=r"(r2), "=r"(r3) : "r"(addr));
}
__device__ __forceinline__ void mma16816(float* d, const unsigned* a, const unsigned* b) {
    asm volatile("mma.sync.aligned.m16n8k16.row.col.f32.f16.f16.f32 "
                 "{%0,%1,%2,%3},{%4,%5,%6,%7},{%8,%9},{%0,%1,%2,%3};\n"
                 : "+f"(d[0]), "+f"(d[1]), "+f"(d[2]), "+f"(d[3])
                 : "r"(a[0]), "r"(a[1]), "r"(a[2]), "r"(a[3]), "r"(b[0]), "r"(b[1]));
}
__device__ __forceinline__ void cp16(uint32_t smem, const void* gmem) {
    asm volatile("cp.async.cg.shared.global [%0], [%1], 16;\n"
                 :: "r"(smem), "l"(gmem));
}
// write-through store: D lines never sit dirty in L2
__device__ __forceinline__ void stwt32(void* p, unsigned v) {
    asm volatile("st.global.wt.b32 [%0], %1;\n" :: "l"(p), "r"(v) : "memory");
}

// ---------------- kernel 1: fused patch extraction + row norms + min init --
// One warp per (b,n) patch row: extract fp16 values for X and Y, write them,
// and accumulate both squared norms in f32 while values are live (saves the
// separate k_sums pass that re-read 10.9 MB).
__global__ void k_prep(const float* __restrict__ x, const float* __restrict__ y) {
    const int tid  = threadIdx.x;
    const int lane = tid & 31;
    const int gw   = blockIdx.x * (blockDim.x >> 5) + (tid >> 5);

    int mi = blockIdx.x * blockDim.x + tid;
    if (mi < 2 * NP) {
        (&g_rowMin[0][0])[mi] = 0xFFFFFFFFu;
        (&g_colMin[0][0])[mi] = 0xFFFFFFFFu;
    }
    if (gw >= 2 * NP) return;
    const int b  = gw / NP;
    const int n  = gw % NP;
    const int py = n / HP, px = n % HP;

    float sx = 0.f, sy = 0.f;
    for (int k = lane; k < KP; k += 32) {
        __half hx = __float2half(0.0f), hy = hx;
        if (k < DFEAT) {
            int c  = k / 49;
            int kk = k % 49;
            int dy = kk / PB, dx = kk % PB;
            int off = ((b * 3 + c) * 96 + (py + dy)) * 96 + (px + dx);
            hx = __float2half(x[off]);
            hy = __float2half(y[off]);
            float qx = __half2float(hx), qy = __half2float(hy);
            sx += qx * qx;
            sy += qy * qy;
        }
        g_Xp[b][n][k] = hx;
        g_Yp[b][n][k] = hy;
    }
    #pragma unroll
    for (int o = 16; o; o >>= 1) {
        sx += __shfl_xor_sync(0xFFFFFFFFu, sx, o);
        sy += __shfl_xor_sync(0xFFFFFFFFu, sy, o);
    }
    if (lane == 0) {
        g_Sx[b][n] = sx;
        g_Sy[b][n] = sy;
    }
}

// ---------------- kernel 3: dist GEMM via HMMA (fused store + rowmin) ------
// round-5/12/13 proven shape: 128x128 block, 256 threads = 8 warps (4m x 2n),
// warp tile m32 x n64, f32 accumulators; D stores via scattered st.wt.
__global__ void k_dist() {
    extern __shared__ __half smemBuf[];
    __half* Ys = smemBuf;                      // 128 x KP
    __half* Xs = smemBuf + 128 * KP;           // 128 x KP
    float* sSy = (float*)(smemBuf + 2 * 128 * KP);
    float* sSx = sSy + 128;

    const int tid  = threadIdx.x;
    const int lane = tid & 31;
    const int wid  = tid >> 5;
    const int b    = blockIdx.z;
    const int rowBase = blockIdx.y * 128;   // targets (Y)
    const int colBase = blockIdx.x * 128;   // inputs  (X)

    // cooperative load via cp.async: 128 rows x 21 uint4 per operand
    const uint4* ybase = (const uint4*)&g_Yp[b][0][0];
    const uint4* xbase = (const uint4*)&g_Xp[b][0][0];
    uint32_t ysAddr = (uint32_t)__cvta_generic_to_shared(Ys);
    uint32_t xsAddr = (uint32_t)__cvta_generic_to_shared(Xs);
    #pragma unroll 3
    for (int idx = tid; idx < 128 * KV4; idx += 256) {
        int r = idx / KV4, c = idx % KV4;
        int gy = min(rowBase + r, NP - 1);
        int gx = min(colBase + r, NP - 1);
        cp16(ysAddr + idx * 16u, &ybase[(size_t)gy * KV4 + c]);
        cp16(xsAddr + idx * 16u, &xbase[(size_t)gx * KV4 + c]);
    }
    asm volatile("cp.async.commit_group;\n" ::: "memory");
    if (tid < 128) sSy[tid] = g_Sy[b][min(rowBase + tid, NP - 1)];
    else           sSx[tid - 128] = g_Sx[b][min(colBase + tid - 128, NP - 1)];
    asm volatile("cp.async.wait_group 0;\n" ::: "memory");
    __syncthreads();

    const int warpM = (wid >> 1) * 32;
    const int warpN = (wid & 1) * 64;

    // ldmatrix per-lane addresses
    int aRow = warpM + (lane & 15);
    uint32_t aAddr0 = ysAddr + (uint32_t)(aRow * KP + (lane >> 4) * 8) * 2u;
    uint32_t aAddr1 = aAddr0 + 16u * KP * 2u;
    int bRow = warpN + (lane & 7) + ((lane >> 4) & 1) * 8;
    int bKc  = (lane >> 3) & 1;
    uint32_t bAddr[4];
    #pragma unroll
    for (int p = 0; p < 4; p++)
        bAddr[p] = xsAddr + (uint32_t)((bRow + p * 16) * KP + bKc * 8) * 2u;

    float acc[2][8][4];
    #pragma unroll
    for (int mi = 0; mi < 2; mi++)
        #pragma unroll
        for (int ni = 0; ni < 8; ni++)
            #pragma unroll
            for (int q = 0; q < 4; q++) acc[mi][ni][q] = 0.f;

    #pragma unroll
    for (int ks = 0; ks < 10; ks++) {
        uint32_t koff = (uint32_t)ks * 32u;   // 16 halves
        unsigned af[2][4];
        ldsm4(af[0][0], af[0][1], af[0][2], af[0][3], aAddr0 + koff);
        ldsm4(af[1][0], af[1][1], af[1][2], af[1][3], aAddr1 + koff);
        unsigned bf[4][4];  // bf[p][0..1] -> ni=2p, bf[p][2..3] -> ni=2p+1
        #pragma unroll
        for (int p = 0; p < 4; p++)
            ldsm4(bf[p][0], bf[p][1], bf[p][2], bf[p][3], bAddr[p] + koff);
        #pragma unroll
        for (int mi = 0; mi < 2; mi++)
            #pragma unroll
            for (int ni = 0; ni < 8; ni++)
                mma16816(acc[mi][ni], af[mi], &bf[ni >> 1][(ni & 1) * 2]);
    }

    // epilogue: dist, fp16 round, write-through store D, rowmin
    const float invd = 1.0f / 147.0f;
    const int qr = lane >> 2, qc = lane & 3;
    __half* Db = &g_D[(size_t)b * NP * NPD];
    #pragma unroll
    for (int mi = 0; mi < 2; mi++) {
        int lr0 = warpM + mi * 16 + qr;
        int lr1 = lr0 + 8;
        int gt0 = rowBase + lr0, gt1 = rowBase + lr1;
        float sy0 = sSy[lr0], sy1 = sSy[lr1];
        float lm0 = __int_as_float(0x7F800000), lm1 = lm0;
        #pragma unroll
        for (int ni = 0; ni < 8; ni++) {
            int lc = warpN + ni * 8 + qc * 2;
            int gi = colBase + lc;
            if (gi < NP) {                       // NP even, pair stays in-range together
                float sx0 = sSx[lc], sx1 = sSx[lc + 1];
                if (gt0 < NP) {
                    __half h0 = __float2half((sy0 + sx0 - 2.0f * acc[mi][ni][0]) * invd);
                    __half h1 = __float2half((sy0 + sx1 - 2.0f * acc[mi][ni][1]) * invd);
                    __half2 hh = __halves2half2(h0, h1);
                    stwt32(&Db[(size_t)gt0 * NPD + gi], *(unsigned*)&hh);
                    lm0 = fminf(lm0, fminf(__half2float(h0), __half2float(h1)));
                }
                if (gt1 < NP) {
                    __half h2 = __float2half((sy1 + sx0 - 2.0f * acc[mi][ni][2]) * invd);
                    __half h3 = __float2half((sy1 + sx1 - 2.0f * acc[mi][ni][3]) * invd);
                    __half2 hh = __halves2half2(h2, h3);
                    stwt32(&Db[(size_t)gt1 * NPD + gi], *(unsigned*)&hh);
                    lm1 = fminf(lm1, fminf(__half2float(h2), __half2float(h3)));
                }
            }
        }
        #pragma unroll
        for (int o = 2; o; o >>= 1) {
            lm0 = fminf(lm0, __shfl_xor_sync(0xFFFFFFFFu, lm0, o));
            lm1 = fminf(lm1, __shfl_xor_sync(0xFFFFFFFFu, lm1, o));
        }
        if (qc == 0) {
            if (gt0 < NP) atomicMin(&g_rowMin[b][gt0], fkey(lm0));
            if (gt1 < NP) atomicMin(&g_rowMin[b][gt1], fkey(lm1));
        }
    }
}

// ---------------- kernel 4: column-min of dist/(rowmin+alpha) --------------
// round-13 proven version: 8 cols/thread (one uint4/row), rows x4, 1016 CTAs
#define CM_CHUNK 64
__device__ __forceinline__ void cm_acc4(float* m, const uint4& v, float inv) {
    float2 f0 = __half22float2(*(const __half2*)&v.x);
    float2 f1 = __half22float2(*(const __half2*)&v.y);
    float2 f2 = __half22float2(*(const __half2*)&v.z);
    float2 f3 = __half22float2(*(const __half2*)&v.w);
    m[0] = fminf(m[0], f0.x * inv); m[1] = fminf(m[1], f0.y * inv);
    m[2] = fminf(m[2], f1.x * inv); m[3] = fminf(m[3], f1.y * inv);
    m[4] = fminf(m[4], f2.x * inv); m[5] = fminf(m[5], f2.y * inv);
    m[6] = fminf(m[6], f3.x * inv); m[7] = fminf(m[7], f3.y * inv);
}
__global__ void k_colmin() {
    __shared__ float sInv[CM_CHUNK];
    const int tid = threadIdx.x;
    const int b   = blockIdx.z;
    const int t0  = blockIdx.y * CM_CHUNK;
    const int nrows = min(CM_CHUNK, NP - t0);
    const float alpha = __half2float(__float2half(0.05f));  // f16-rounded ALPHA

    if (tid < nrows)
        sInv[tid] = 1.0f / (funkey(g_rowMin[b][t0 + tid]) + alpha);
    __syncthreads();

    const int col0 = (blockIdx.x * 256 + tid) * 8;
    if (col0 >= NP) return;
    const bool full = (col0 + 8 <= NPD);   // always true for col0 <= 8096

    float m[8];
    #pragma unroll
    for (int j = 0; j < 8; j++) m[j] = __int_as_float(0x7F800000);

    const __half* Db = &g_D[(size_t)b * NP * NPD];
    if (full) {
        const char* base = (const char*)(Db + (size_t)t0 * NPD + col0);
        const size_t stride = (size_t)NPD * sizeof(__half);
        int r = 0;
        for (; r + 4 <= nrows; r += 4) {
            uint4 v[4];
            #pragma unroll
            for (int u = 0; u < 4; u++)
                v[u] = __ldcs((const uint4*)(base + (size_t)(r + u) * stride));
            #pragma unroll
            for (int u = 0; u < 4; u++)
                cm_acc4(m, v[u], sInv[r + u]);
        }
        for (; r < nrows; r++) {
            uint4 v = __ldcs((const uint4*)(base + (size_t)r * stride));
            cm_acc4(m, v, sInv[r]);
        }
    }
    #pragma unroll
    for (int j = 0; j < 8; j++)
        if (col0 + j < NP) atomicMin(&g_colMin[b][col0 + j], fkey(m[j]));
}

// ---------------- kernel 5: final mean, write scalar (fp32 output) ---------
__global__ void k_final(float* __restrict__ out) {
    __shared__ float r0[512], r1[512];
    int tid = threadIdx.x;
    float s0 = 0.f, s1 = 0.f;
    for (int i = tid; i < NP; i += 512) {
        s0 += funkey(g_colMin[0][i]);
        s1 += funkey(g_colMin[1][i]);
    }
    r0[tid] = s0; r1[tid] = s1;
    __syncthreads();
    for (int o = 256; o; o >>= 1) {
        if (tid < o) { r0[tid] += r0[tid + o]; r1[tid] += r1[tid + o]; }
        __syncthreads();
    }
    if (tid == 0) {
        float loss = (r0[0] + r1[0]) / (2.0f * NP);
        out[0] = loss;
    }
}

// ---------------- launch ---------------------------------------------------
extern "C" void kernel_launch(void* const* d_in, const int* in_sizes, int n_in,
                              void* d_out, int out_size) {
    const float* x = (const float*)d_in[0];
    const float* y = (const float*)d_in[1];
    float* out = (float*)d_out;

    const int distSmem = 2 * 128 * KP * 2 + 2 * 128 * 4;   // 87040 B
    cudaFuncSetAttribute(k_dist, cudaFuncAttributeMaxDynamicSharedMemorySize, distSmem);

    {
        int warps = 2 * NP;                    // one warp per (b, n)
        k_prep<<<(warps + 7) / 8, 256>>>(x, y);
    }
    {
        dim3 grid((NP + 127) / 128, (NP + 127) / 128, 2);   // 64 x 64 x 2
        k_dist<<<grid, 256, distSmem>>>();
    }
    {
        dim3 grid((NP + 2047) / 2048, (NP + CM_CHUNK - 1) / CM_CHUNK, 2);   // 4 x 127 x 2
        k_colmin<<<grid, 256>>>();
    }
    k_final<<<1, 512>>>(out);
}